// round 2
// baseline (speedup 1.0000x reference)
#include <cuda_runtime.h>

#define BATCH   262144
#define NIND    32
#define NDEP    16
#define EPSV    1e-7f
#define ITERS   6

typedef unsigned long long u64;

// ---- packed f32x2 helpers (Blackwell sm_103a) ----
__device__ __forceinline__ u64 pack2(float a, float b) {
    u64 r; asm("mov.b64 %0, {%1, %2};" : "=l"(r) : "f"(a), "f"(b)); return r;
}
__device__ __forceinline__ void unpack2(u64 v, float &a, float &b) {
    asm("mov.b64 {%0, %1}, %2;" : "=f"(a), "=f"(b) : "l"(v));
}
__device__ __forceinline__ u64 ffma2(u64 a, u64 b, u64 c) {
    u64 d; asm("fma.rn.f32x2 %0, %1, %2, %3;" : "=l"(d) : "l"(a), "l"(b), "l"(c));
    return d;
}
__device__ __forceinline__ float frcp(float x) {
    float r; asm("rcp.approx.f32 %0, %1;" : "=f"(r) : "f"(x)); return r;
}

// Each thread solves 2 batch elements, lane-packed into f32x2.
// Jacobi-preconditioned Neumann: A = Dg + Off;  y <- invDg*(rhs - Off*y)
__global__ __launch_bounds__(128)
void clefo_kernel(const float* __restrict__ X, const float* __restrict__ Z,
                  const float* __restrict__ Ups, const float* __restrict__ Bm,
                  const float* __restrict__ Th,  const float* __restrict__ Ga,
                  const float* __restrict__ La,  float* __restrict__ out)
{
    // Coefficients pre-duplicated as (w,w) pairs for direct f32x2 operands.
    __shared__ u64 sW[NDEP][2 * NIND];   // [j][k]: k<32 -> Bmat, k>=32 -> Theta
    __shared__ u64 sL[NDEP][NIND];       // Lam
    __shared__ u64 sOff[NDEP][NDEP];     // -Gamma off-diag, 0 on diag
    __shared__ float sUps[NDEP];
    __shared__ float sGd[NDEP];          // 1+eps - Gamma_ii

    const int tid = threadIdx.x;
    for (int idx = tid; idx < NDEP * 2 * NIND; idx += blockDim.x) {
        int j = idx >> 6, k = idx & 63;
        float w = (k < NIND) ? Bm[j * NIND + k] : Th[j * NIND + (k - NIND)];
        sW[j][k] = pack2(w, w);
    }
    for (int idx = tid; idx < NDEP * NIND; idx += blockDim.x) {
        int j = idx >> 5, k = idx & 31;
        float w = La[j * NIND + k];
        sL[j][k] = pack2(w, w);
    }
    for (int idx = tid; idx < NDEP * NDEP; idx += blockDim.x) {
        int i = idx >> 4, j = idx & 15;
        float v = (i == j) ? 0.0f : -Ga[idx];
        sOff[i][j] = pack2(v, v);
    }
    if (tid < NDEP) {
        sUps[tid] = Ups[tid];
        sGd[tid]  = 1.0f + EPSV - Ga[tid * NDEP + tid];
    }
    __syncthreads();

    const long long gid = (long long)blockIdx.x * blockDim.x + tid;
    const long long e0  = gid * 2;        // this thread's pair: e0, e0+1

    // ---- Phase 1: rhs = Ups + Bm*x + Th*z ;  d = La*x  (packed over the pair)
    u64 rhs[NDEP], dd[NDEP];
#pragma unroll
    for (int j = 0; j < NDEP; ++j) {
        float u = sUps[j];
        rhs[j] = pack2(u, u);
        dd[j]  = 0ull;                    // bit pattern of (0.f, 0.f)
    }

    const float4* Xa = (const float4*)(X + e0 * NIND);
    const float4* Xb = (const float4*)(X + (e0 + 1) * NIND);
#pragma unroll 1
    for (int c = 0; c < NIND / 4; ++c) {
        float4 va = Xa[c], vb = Xb[c];
        u64 xp[4];
        xp[0] = pack2(va.x, vb.x); xp[1] = pack2(va.y, vb.y);
        xp[2] = pack2(va.z, vb.z); xp[3] = pack2(va.w, vb.w);
#pragma unroll
        for (int kk = 0; kk < 4; ++kk) {
            int k = c * 4 + kk;
#pragma unroll
            for (int j = 0; j < NDEP; ++j) rhs[j] = ffma2(xp[kk], sW[j][k], rhs[j]);
#pragma unroll
            for (int j = 0; j < NDEP; ++j) dd[j]  = ffma2(xp[kk], sL[j][k], dd[j]);
        }
    }

    const float4* Za = (const float4*)(Z + e0 * NIND);
    const float4* Zb = (const float4*)(Z + (e0 + 1) * NIND);
#pragma unroll 1
    for (int c = 0; c < NIND / 4; ++c) {
        float4 va = Za[c], vb = Zb[c];
        u64 xp[4];
        xp[0] = pack2(va.x, vb.x); xp[1] = pack2(va.y, vb.y);
        xp[2] = pack2(va.z, vb.z); xp[3] = pack2(va.w, vb.w);
#pragma unroll
        for (int kk = 0; kk < 4; ++kk) {
            int k = NIND + c * 4 + kk;
#pragma unroll
            for (int j = 0; j < NDEP; ++j) rhs[j] = ffma2(xp[kk], sW[j][k], rhs[j]);
        }
    }

    // ---- Phase 2: diagonal setup  Dg_i = (1+eps - Gamma_ii) - d_i
    u64 cc[NDEP], ninv[NDEP], y[NDEP];
#pragma unroll
    for (int i = 0; i < NDEP; ++i) {
        float da, db;  unpack2(dd[i], da, db);
        float g = sGd[i];
        float ia = frcp(g - da);
        float ib = frcp(g - db);
        float ra, rb;  unpack2(rhs[i], ra, rb);
        cc[i]   = pack2(ra * ia, rb * ib);   // invDg * rhs
        ninv[i] = pack2(-ia, -ib);           // -invDg
        y[i]    = cc[i];
    }

    // ---- Phase 3: Neumann iterations  y <- cc - invDg*(Off*y)
#pragma unroll 1
    for (int it = 0; it < ITERS; ++it) {
        u64 t[NDEP];
#pragma unroll
        for (int i = 0; i < NDEP; ++i) {
            u64 acc = 0ull;
#pragma unroll
            for (int j = 0; j < NDEP; ++j) acc = ffma2(sOff[i][j], y[j], acc);
            t[i] = acc;
        }
#pragma unroll
        for (int i = 0; i < NDEP; ++i) y[i] = ffma2(ninv[i], t[i], cc[i]);
    }

    // ---- Store: unpack pair and write both rows with float4 stores
    float4* o0 = (float4*)(out + e0 * NDEP);
    float4* o1 = (float4*)(out + (e0 + 1) * NDEP);
#pragma unroll
    for (int q = 0; q < 4; ++q) {
        float a0, b0, a1, b1, a2, b2, a3, b3;
        unpack2(y[4 * q + 0], a0, b0);
        unpack2(y[4 * q + 1], a1, b1);
        unpack2(y[4 * q + 2], a2, b2);
        unpack2(y[4 * q + 3], a3, b3);
        o0[q] = make_float4(a0, a1, a2, a3);
        o1[q] = make_float4(b0, b1, b2, b3);
    }
}

extern "C" void kernel_launch(void* const* d_in, const int* in_sizes, int n_in,
                              void* d_out, int out_size)
{
    const float* X  = (const float*)d_in[0];
    const float* Z  = (const float*)d_in[1];
    const float* Up = (const float*)d_in[2];
    const float* Bm = (const float*)d_in[3];
    const float* Th = (const float*)d_in[4];
    const float* Ga = (const float*)d_in[5];
    const float* La = (const float*)d_in[6];
    float* out = (float*)d_out;

    const int threads = 128;
    const int total_threads = BATCH / 2;      // 2 elements per thread
    const int blocks = total_threads / threads;
    clefo_kernel<<<blocks, threads>>>(X, Z, Up, Bm, Th, Ga, La, out);
}

// round 3
// speedup vs baseline: 1.2788x; 1.2788x over previous
#include <cuda_runtime.h>

#define BATCH   262144
#define NIND    32
#define NDEP    16
#define EPSV    1e-7f
#define ITERS   4

typedef unsigned long long u64;

// ---- packed f32x2 helpers (Blackwell sm_103a) ----
__device__ __forceinline__ u64 pack2(float a, float b) {
    u64 r; asm("mov.b64 %0, {%1, %2};" : "=l"(r) : "f"(a), "f"(b)); return r;
}
__device__ __forceinline__ void unpack2(u64 v, float &a, float &b) {
    asm("mov.b64 {%0, %1}, %2;" : "=f"(a), "=f"(b) : "l"(v));
}
__device__ __forceinline__ u64 ffma2(u64 a, u64 b, u64 c) {
    u64 d; asm("fma.rn.f32x2 %0, %1, %2, %3;" : "=l"(d) : "l"(a), "l"(b), "l"(c));
    return d;
}
__device__ __forceinline__ float frcp(float x) {
    float r; asm("rcp.approx.f32 %0, %1;" : "=f"(r) : "f"(x)); return r;
}

// One batch element per thread; f32x2 packs OUTPUT ROWS (2i, 2i+1).
// Jacobi-preconditioned Neumann: A = Dg + Off;  y <- invDg*rhs - invDg*(Off*y)
__global__ __launch_bounds__(128, 4)
void clefo_kernel(const float* __restrict__ X, const float* __restrict__ Z,
                  const float* __restrict__ Ups, const float* __restrict__ Bm,
                  const float* __restrict__ Th,  const float* __restrict__ Ga,
                  const float* __restrict__ La,  float* __restrict__ out)
{
    // Weights paired across adjacent output rows, vector-loadable (LDS.128).
    __shared__ ulonglong2 sW2[2 * NIND][4];   // [k][q2]: rows (4q2..4q2+3); k<32->Bmat, else Theta
    __shared__ ulonglong2 sL2[NIND][4];       // Lam
    __shared__ ulonglong2 sOff2[NDEP][4];     // column j, rows paired; -Gamma off-diag, 0 diag
    __shared__ u64 sGd2[8];                   // (1+eps - Gamma_ii) pairs
    __shared__ u64 sUps2[8];

    const int tid = threadIdx.x;
    for (int idx = tid; idx < 2 * NIND * 8; idx += 128) {
        int k = idx >> 3, j2 = idx & 7;
        int r0 = 2 * j2, r1 = r0 + 1;
        float w0, w1;
        if (k < NIND) { w0 = Bm[r0 * NIND + k];          w1 = Bm[r1 * NIND + k]; }
        else          { w0 = Th[r0 * NIND + (k - NIND)]; w1 = Th[r1 * NIND + (k - NIND)]; }
        ((u64*)&sW2[k][0])[j2] = pack2(w0, w1);
    }
    for (int idx = tid; idx < NIND * 8; idx += 128) {
        int k = idx >> 3, j2 = idx & 7;
        ((u64*)&sL2[k][0])[j2] = pack2(La[(2 * j2) * NIND + k], La[(2 * j2 + 1) * NIND + k]);
    }
    for (int idx = tid; idx < NDEP * 8; idx += 128) {
        int j = idx >> 3, i2 = idx & 7;
        int i0 = 2 * i2, i1 = i0 + 1;
        float v0 = (i0 == j) ? 0.0f : -Ga[i0 * NDEP + j];
        float v1 = (i1 == j) ? 0.0f : -Ga[i1 * NDEP + j];
        ((u64*)&sOff2[j][0])[i2] = pack2(v0, v1);
    }
    if (tid < 8) {
        sUps2[tid] = pack2(Ups[2 * tid], Ups[2 * tid + 1]);
        sGd2[tid]  = pack2(1.0f + EPSV - Ga[(2 * tid) * NDEP + 2 * tid],
                           1.0f + EPSV - Ga[(2 * tid + 1) * NDEP + 2 * tid + 1]);
    }
    __syncthreads();

    const int e = blockIdx.x * 128 + tid;

    // ---- Phase 1: rhs = Ups + Bm*x + Th*z ;  d = La*x   (rows packed in pairs)
    u64 rhs2[8], dd2[8];
#pragma unroll
    for (int q = 0; q < 8; ++q) { rhs2[q] = sUps2[q]; dd2[q] = 0ull; }

    const float4* Xv = (const float4*)(X + (size_t)e * NIND);
#pragma unroll 2
    for (int c = 0; c < NIND / 4; ++c) {
        float4 v = Xv[c];
        float xs0 = v.x, xs1 = v.y, xs2 = v.z, xs3 = v.w;
        float xs[4] = {xs0, xs1, xs2, xs3};
#pragma unroll
        for (int kk = 0; kk < 4; ++kk) {
            int k = 4 * c + kk;
            u64 xd = pack2(xs[kk], xs[kk]);
#pragma unroll
            for (int q2 = 0; q2 < 4; ++q2) {
                ulonglong2 w = sW2[k][q2];
                rhs2[2 * q2]     = ffma2(xd, w.x, rhs2[2 * q2]);
                rhs2[2 * q2 + 1] = ffma2(xd, w.y, rhs2[2 * q2 + 1]);
                ulonglong2 l = sL2[k][q2];
                dd2[2 * q2]      = ffma2(xd, l.x, dd2[2 * q2]);
                dd2[2 * q2 + 1]  = ffma2(xd, l.y, dd2[2 * q2 + 1]);
            }
        }
    }

    const float4* Zv = (const float4*)(Z + (size_t)e * NIND);
#pragma unroll 2
    for (int c = 0; c < NIND / 4; ++c) {
        float4 v = Zv[c];
        float xs[4] = {v.x, v.y, v.z, v.w};
#pragma unroll
        for (int kk = 0; kk < 4; ++kk) {
            int k = NIND + 4 * c + kk;
            u64 xd = pack2(xs[kk], xs[kk]);
#pragma unroll
            for (int q2 = 0; q2 < 4; ++q2) {
                ulonglong2 w = sW2[k][q2];
                rhs2[2 * q2]     = ffma2(xd, w.x, rhs2[2 * q2]);
                rhs2[2 * q2 + 1] = ffma2(xd, w.y, rhs2[2 * q2 + 1]);
            }
        }
    }

    // ---- Phase 2: diagonal setup  Dg_i = (1+eps - Gamma_ii) - d_i
    u64 cc2[8], ninv2[8], y2[8];
#pragma unroll
    for (int q = 0; q < 8; ++q) {
        float da, db, ga, gb, ra, rb;
        unpack2(dd2[q], da, db);
        unpack2(sGd2[q], ga, gb);
        unpack2(rhs2[q], ra, rb);
        float ia = frcp(ga - da);
        float ib = frcp(gb - db);
        cc2[q]   = pack2(ra * ia, rb * ib);   // invDg * rhs
        ninv2[q] = pack2(-ia, -ib);           // -invDg
        y2[q]    = cc2[q];
    }

    // ---- Phase 3: Neumann iterations  y <- cc - invDg*(Off*y)
#pragma unroll 1
    for (int it = 0; it < ITERS; ++it) {
        u64 acc[8];
#pragma unroll
        for (int q = 0; q < 8; ++q) acc[q] = 0ull;
#pragma unroll
        for (int j = 0; j < NDEP; ++j) {
            float a, b; unpack2(y2[j >> 1], a, b);
            float yj = (j & 1) ? b : a;
            u64 yd = pack2(yj, yj);
#pragma unroll
            for (int q2 = 0; q2 < 4; ++q2) {
                ulonglong2 o = sOff2[j][q2];
                acc[2 * q2]     = ffma2(yd, o.x, acc[2 * q2]);
                acc[2 * q2 + 1] = ffma2(yd, o.y, acc[2 * q2 + 1]);
            }
        }
#pragma unroll
        for (int q = 0; q < 8; ++q) y2[q] = ffma2(ninv2[q], acc[q], cc2[q]);
    }

    // ---- Store: row-packed pairs are already in output order -> STG.128
    ulonglong2* ov = (ulonglong2*)(out + (size_t)e * NDEP);
#pragma unroll
    for (int q = 0; q < 4; ++q) ov[q] = make_ulonglong2(y2[2 * q], y2[2 * q + 1]);
}

extern "C" void kernel_launch(void* const* d_in, const int* in_sizes, int n_in,
                              void* d_out, int out_size)
{
    const float* X  = (const float*)d_in[0];
    const float* Z  = (const float*)d_in[1];
    const float* Up = (const float*)d_in[2];
    const float* Bm = (const float*)d_in[3];
    const float* Th = (const float*)d_in[4];
    const float* Ga = (const float*)d_in[5];
    const float* La = (const float*)d_in[6];
    float* out = (float*)d_out;

    const int threads = 128;
    const int blocks  = BATCH / threads;   // one element per thread
    clefo_kernel<<<blocks, threads>>>(X, Z, Up, Bm, Th, Ga, La, out);
}

// round 5
// speedup vs baseline: 2.1103x; 1.6502x over previous
#include <cuda_runtime.h>

#define BATCH   262144
#define NIND    32
#define NDEP    16
#define EPSV    1e-7f
#define ITERS   3

typedef unsigned long long u64;

// ---- packed f32x2 helpers (Blackwell sm_103a) ----
__device__ __forceinline__ u64 pack2(float a, float b) {
    u64 r; asm("mov.b64 %0, {%1, %2};" : "=l"(r) : "f"(a), "f"(b)); return r;
}
__device__ __forceinline__ void unpack2(u64 v, float &a, float &b) {
    asm("mov.b64 {%0, %1}, %2;" : "=f"(a), "=f"(b) : "l"(v));
}
__device__ __forceinline__ u64 ffma2(u64 a, u64 b, u64 c) {
    u64 d; asm("fma.rn.f32x2 %0, %1, %2, %3;" : "=l"(d) : "l"(a), "l"(b), "l"(c));
    return d;
}
__device__ __forceinline__ float frcp(float x) {
    float r; asm("rcp.approx.f32 %0, %1;" : "=f"(r) : "f"(x)); return r;
}

// TWO batch elements per thread; f32x2 packs OUTPUT ROWS (2i, 2i+1).
// Every weight pair loaded from smem is reused for both elements (2 B/MAC).
// Jacobi-preconditioned Neumann with +Gamma / +invDg (no negations):
//   y <- cc + invDg * (GammaOff * y),  cc = invDg * rhs
__global__ __launch_bounds__(64, 5)
void clefo_kernel(const float* __restrict__ X, const float* __restrict__ Z,
                  const float* __restrict__ Ups, const float* __restrict__ Bm,
                  const float* __restrict__ Th,  const float* __restrict__ Ga,
                  const float* __restrict__ La,  float* __restrict__ out)
{
    // Weights paired across adjacent output rows, vector-loadable (LDS.128).
    __shared__ ulonglong2 sW2[2 * NIND][4];   // [k][q2]: rows (4q2..4q2+3); k<32->Bmat, else Theta
    __shared__ ulonglong2 sL2[NIND][4];       // Lam
    __shared__ ulonglong2 sOff2[NDEP][4];     // column j, rows paired; +Gamma off-diag, 0 diag
    __shared__ u64 sGd2[8];                   // (1+eps - Gamma_ii) pairs
    __shared__ u64 sUps2[8];

    const int tid = threadIdx.x;
    for (int idx = tid; idx < 2 * NIND * 8; idx += 64) {
        int k = idx >> 3, j2 = idx & 7;
        int r0 = 2 * j2, r1 = r0 + 1;
        float w0, w1;
        if (k < NIND) { w0 = Bm[r0 * NIND + k];          w1 = Bm[r1 * NIND + k]; }
        else          { w0 = Th[r0 * NIND + (k - NIND)]; w1 = Th[r1 * NIND + (k - NIND)]; }
        ((u64*)&sW2[k][0])[j2] = pack2(w0, w1);
    }
    for (int idx = tid; idx < NIND * 8; idx += 64) {
        int k = idx >> 3, j2 = idx & 7;
        ((u64*)&sL2[k][0])[j2] = pack2(La[(2 * j2) * NIND + k], La[(2 * j2 + 1) * NIND + k]);
    }
    for (int idx = tid; idx < NDEP * 8; idx += 64) {
        int j = idx >> 3, i2 = idx & 7;
        int i0 = 2 * i2, i1 = i0 + 1;
        float v0 = (i0 == j) ? 0.0f : Ga[i0 * NDEP + j];
        float v1 = (i1 == j) ? 0.0f : Ga[i1 * NDEP + j];
        ((u64*)&sOff2[j][0])[i2] = pack2(v0, v1);
    }
    if (tid < 8) {
        sUps2[tid] = pack2(Ups[2 * tid], Ups[2 * tid + 1]);
        sGd2[tid]  = pack2(1.0f + EPSV - Ga[(2 * tid) * NDEP + 2 * tid],
                           1.0f + EPSV - Ga[(2 * tid + 1) * NDEP + 2 * tid + 1]);
    }
    __syncthreads();

    // Two elements per thread, 128 elements per block.
    const size_t ea = (size_t)blockIdx.x * 128 + tid;        // element A
    const size_t eb = ea + 64;                               // element B

    // ---- Phase 1: rhs = Ups + Bm*x + Th*z ;  d = La*x   (rows packed in pairs)
    u64 rhsA[8], rhsB[8], ddA[8], ddB[8];
#pragma unroll
    for (int q = 0; q < 8; ++q) {
        rhsA[q] = sUps2[q]; rhsB[q] = sUps2[q];
        ddA[q] = 0ull;      ddB[q] = 0ull;
    }

    {
        const float4* Xa = (const float4*)(X + ea * NIND);
        const float4* Xb = (const float4*)(X + eb * NIND);
#pragma unroll 1
        for (int c = 0; c < NIND / 4; ++c) {
            float4 va = Xa[c], vb = Xb[c];
            float xa[4] = {va.x, va.y, va.z, va.w};
            float xb[4] = {vb.x, vb.y, vb.z, vb.w};
#pragma unroll
            for (int kk = 0; kk < 4; ++kk) {
                int k = 4 * c + kk;
                u64 xda = pack2(xa[kk], xa[kk]);
                u64 xdb = pack2(xb[kk], xb[kk]);
#pragma unroll
                for (int q2 = 0; q2 < 4; ++q2) {
                    ulonglong2 w = sW2[k][q2];
                    rhsA[2 * q2]     = ffma2(xda, w.x, rhsA[2 * q2]);
                    rhsA[2 * q2 + 1] = ffma2(xda, w.y, rhsA[2 * q2 + 1]);
                    rhsB[2 * q2]     = ffma2(xdb, w.x, rhsB[2 * q2]);
                    rhsB[2 * q2 + 1] = ffma2(xdb, w.y, rhsB[2 * q2 + 1]);
                    ulonglong2 l = sL2[k][q2];
                    ddA[2 * q2]      = ffma2(xda, l.x, ddA[2 * q2]);
                    ddA[2 * q2 + 1]  = ffma2(xda, l.y, ddA[2 * q2 + 1]);
                    ddB[2 * q2]      = ffma2(xdb, l.x, ddB[2 * q2]);
                    ddB[2 * q2 + 1]  = ffma2(xdb, l.y, ddB[2 * q2 + 1]);
                }
            }
        }
    }
    {
        const float4* Za = (const float4*)(Z + ea * NIND);
        const float4* Zb = (const float4*)(Z + eb * NIND);
#pragma unroll 1
        for (int c = 0; c < NIND / 4; ++c) {
            float4 va = Za[c], vb = Zb[c];
            float xa[4] = {va.x, va.y, va.z, va.w};
            float xb[4] = {vb.x, vb.y, vb.z, vb.w};
#pragma unroll
            for (int kk = 0; kk < 4; ++kk) {
                int k = NIND + 4 * c + kk;
                u64 xda = pack2(xa[kk], xa[kk]);
                u64 xdb = pack2(xb[kk], xb[kk]);
#pragma unroll
                for (int q2 = 0; q2 < 4; ++q2) {
                    ulonglong2 w = sW2[k][q2];
                    rhsA[2 * q2]     = ffma2(xda, w.x, rhsA[2 * q2]);
                    rhsA[2 * q2 + 1] = ffma2(xda, w.y, rhsA[2 * q2 + 1]);
                    rhsB[2 * q2]     = ffma2(xdb, w.x, rhsB[2 * q2]);
                    rhsB[2 * q2 + 1] = ffma2(xdb, w.y, rhsB[2 * q2 + 1]);
                }
            }
        }
    }

    // ---- Phase 2: Dg_i = (1+eps - Gamma_ii) - d_i ; cc = rhs/Dg ; keep +invDg
    u64 ccA[8], ccB[8], invA[8], invB[8], yA[8], yB[8];
#pragma unroll
    for (int q = 0; q < 8; ++q) {
        float g0, g1; unpack2(sGd2[q], g0, g1);
        float da0, da1, ra0, ra1;
        unpack2(ddA[q], da0, da1); unpack2(rhsA[q], ra0, ra1);
        float ia0 = frcp(g0 - da0), ia1 = frcp(g1 - da1);
        ccA[q]  = pack2(ra0 * ia0, ra1 * ia1);
        invA[q] = pack2(ia0, ia1);
        yA[q]   = ccA[q];
        float db0, db1, rb0, rb1;
        unpack2(ddB[q], db0, db1); unpack2(rhsB[q], rb0, rb1);
        float ib0 = frcp(g0 - db0), ib1 = frcp(g1 - db1);
        ccB[q]  = pack2(rb0 * ib0, rb1 * ib1);
        invB[q] = pack2(ib0, ib1);
        yB[q]   = ccB[q];
    }

    // ---- Phase 3: Neumann iterations  y <- cc + invDg*(GammaOff*y)
#pragma unroll 1
    for (int it = 0; it < ITERS; ++it) {
        u64 accA[8], accB[8];
#pragma unroll
        for (int q = 0; q < 8; ++q) { accA[q] = 0ull; accB[q] = 0ull; }
#pragma unroll
        for (int j = 0; j < NDEP; ++j) {
            float a0, a1; unpack2(yA[j >> 1], a0, a1);
            float ya = (j & 1) ? a1 : a0;
            u64 yda = pack2(ya, ya);
            float b0, b1; unpack2(yB[j >> 1], b0, b1);
            float yb = (j & 1) ? b1 : b0;
            u64 ydb = pack2(yb, yb);
#pragma unroll
            for (int q2 = 0; q2 < 4; ++q2) {
                ulonglong2 o = sOff2[j][q2];
                accA[2 * q2]     = ffma2(yda, o.x, accA[2 * q2]);
                accA[2 * q2 + 1] = ffma2(yda, o.y, accA[2 * q2 + 1]);
                accB[2 * q2]     = ffma2(ydb, o.x, accB[2 * q2]);
                accB[2 * q2 + 1] = ffma2(ydb, o.y, accB[2 * q2 + 1]);
            }
        }
#pragma unroll
        for (int q = 0; q < 8; ++q) {
            yA[q] = ffma2(invA[q], accA[q], ccA[q]);
            yB[q] = ffma2(invB[q], accB[q], ccB[q]);
        }
    }

    // ---- Store: row-packed pairs are already in output order -> STG.128
    ulonglong2* ova = (ulonglong2*)(out + ea * NDEP);
    ulonglong2* ovb = (ulonglong2*)(out + eb * NDEP);
#pragma unroll
    for (int q = 0; q < 4; ++q) ova[q] = make_ulonglong2(yA[2 * q], yA[2 * q + 1]);
#pragma unroll
    for (int q = 0; q < 4; ++q) ovb[q] = make_ulonglong2(yB[2 * q], yB[2 * q + 1]);
}

extern "C" void kernel_launch(void* const* d_in, const int* in_sizes, int n_in,
                              void* d_out, int out_size)
{
    const float* X  = (const float*)d_in[0];
    const float* Z  = (const float*)d_in[1];
    const float* Up = (const float*)d_in[2];
    const float* Bm = (const float*)d_in[3];
    const float* Th = (const float*)d_in[4];
    const float* Ga = (const float*)d_in[5];
    const float* La = (const float*)d_in[6];
    float* out = (float*)d_out;

    const int threads = 64;
    const int blocks  = BATCH / (2 * threads);   // two elements per thread
    clefo_kernel<<<blocks, threads>>>(X, Z, Up, Bm, Th, Ga, La, out);
}

// round 6
// speedup vs baseline: 2.9713x; 1.4080x over previous
#include <cuda_runtime.h>

#define BATCH   262144
#define NIND    32
#define NDEP    16
#define EPSV    1e-7f
#define ITERS   2

typedef unsigned long long u64;

// ---- packed f32x2 helpers (Blackwell sm_103a) ----
__device__ __forceinline__ u64 pack2(float a, float b) {
    u64 r; asm("mov.b64 %0, {%1, %2};" : "=l"(r) : "f"(a), "f"(b)); return r;
}
__device__ __forceinline__ u64 dup2(float a) {
    u64 r; asm("mov.b64 %0, {%1, %1};" : "=l"(r) : "f"(a)); return r;
}
__device__ __forceinline__ void unpack2(u64 v, float &a, float &b) {
    asm("mov.b64 {%0, %1}, %2;" : "=f"(a), "=f"(b) : "l"(v));
}
__device__ __forceinline__ u64 ffma2(u64 a, u64 b, u64 c) {
    u64 d; asm("fma.rn.f32x2 %0, %1, %2, %3;" : "=l"(d) : "l"(a), "l"(b), "l"(c));
    return d;
}
__device__ __forceinline__ float frcp(float x) {
    float r; asm("rcp.approx.f32 %0, %1;" : "=f"(r) : "f"(x)); return r;
}

#define ROWSTRIDE 33   // floats per staged row (conflict-free scalar access)

// TWO batch elements per thread; f32x2 packs OUTPUT ROWS (2i, 2i+1).
// Inputs staged through smem with coalesced LDG (strided-row wavefront fix).
// Jacobi-preconditioned Neumann: y <- cc + invDg*(GammaOff*y), cc = invDg*rhs
__global__ __launch_bounds__(64, 6)
void clefo_kernel(const float* __restrict__ X, const float* __restrict__ Z,
                  const float* __restrict__ Ups, const float* __restrict__ Bm,
                  const float* __restrict__ Th,  const float* __restrict__ Ga,
                  const float* __restrict__ La,  float* __restrict__ out)
{
    __shared__ ulonglong2 sW2[2 * NIND][4];   // [k][q2]: rows (4q2..4q2+3); k<32->Bmat, else Theta
    __shared__ ulonglong2 sL2[NIND][4];       // Lam
    __shared__ ulonglong2 sOff2[NDEP][4];     // column j, rows paired; +Gamma off-diag, 0 diag
    __shared__ u64 sGd2[8];                   // (1+eps - Gamma_ii) pairs
    __shared__ u64 sUps2[8];
    __shared__ float sStage[128 * ROWSTRIDE]; // one block-slab of X or Z (reused)

    const int tid = threadIdx.x;

    // ---- weight prep (once) ----
    for (int idx = tid; idx < 2 * NIND * 8; idx += 64) {
        int k = idx >> 3, j2 = idx & 7;
        int r0 = 2 * j2, r1 = r0 + 1;
        float w0, w1;
        if (k < NIND) { w0 = Bm[r0 * NIND + k];          w1 = Bm[r1 * NIND + k]; }
        else          { w0 = Th[r0 * NIND + (k - NIND)]; w1 = Th[r1 * NIND + (k - NIND)]; }
        ((u64*)&sW2[k][0])[j2] = pack2(w0, w1);
    }
    for (int idx = tid; idx < NIND * 8; idx += 64) {
        int k = idx >> 3, j2 = idx & 7;
        ((u64*)&sL2[k][0])[j2] = pack2(La[(2 * j2) * NIND + k], La[(2 * j2 + 1) * NIND + k]);
    }
    for (int idx = tid; idx < NDEP * 8; idx += 64) {
        int j = idx >> 3, i2 = idx & 7;
        int i0 = 2 * i2, i1 = i0 + 1;
        float v0 = (i0 == j) ? 0.0f : Ga[i0 * NDEP + j];
        float v1 = (i1 == j) ? 0.0f : Ga[i1 * NDEP + j];
        ((u64*)&sOff2[j][0])[i2] = pack2(v0, v1);
    }
    if (tid < 8) {
        sUps2[tid] = pack2(Ups[2 * tid], Ups[2 * tid + 1]);
        sGd2[tid]  = pack2(1.0f + EPSV - Ga[(2 * tid) * NDEP + 2 * tid],
                           1.0f + EPSV - Ga[(2 * tid + 1) * NDEP + 2 * tid + 1]);
    }

    // ---- stage X slab (coalesced global -> padded smem) ----
    const size_t base = (size_t)blockIdx.x * 128;
    {
        const float4* src = (const float4*)(X + base * NIND);
#pragma unroll
        for (int i = 0; i < 16; ++i) {
            int idx = tid + 64 * i;                  // float4 index in slab
            float4 v = src[idx];
            int row = idx >> 3, c0 = (idx & 7) << 2;
            float* dst = &sStage[row * ROWSTRIDE + c0];
            dst[0] = v.x; dst[1] = v.y; dst[2] = v.z; dst[3] = v.w;
        }
    }
    __syncthreads();

    // ---- Phase 1a: X-loop  (rhs += Bm*x ; d = La*x), rows packed in pairs
    u64 rhsA[8], rhsB[8], ddA[8], ddB[8];
#pragma unroll
    for (int q = 0; q < 8; ++q) {
        rhsA[q] = sUps2[q]; rhsB[q] = sUps2[q];
        ddA[q] = 0ull;      ddB[q] = 0ull;
    }
    const float* rowA = &sStage[tid * ROWSTRIDE];
    const float* rowB = &sStage[(tid + 64) * ROWSTRIDE];

#pragma unroll 1
    for (int c = 0; c < NIND / 4; ++c) {
#pragma unroll
        for (int kk = 0; kk < 4; ++kk) {
            int k = 4 * c + kk;
            u64 xda = dup2(rowA[k]);
            u64 xdb = dup2(rowB[k]);
#pragma unroll
            for (int q2 = 0; q2 < 4; ++q2) {
                ulonglong2 w = sW2[k][q2];
                rhsA[2 * q2]     = ffma2(xda, w.x, rhsA[2 * q2]);
                rhsA[2 * q2 + 1] = ffma2(xda, w.y, rhsA[2 * q2 + 1]);
                rhsB[2 * q2]     = ffma2(xdb, w.x, rhsB[2 * q2]);
                rhsB[2 * q2 + 1] = ffma2(xdb, w.y, rhsB[2 * q2 + 1]);
                ulonglong2 l = sL2[k][q2];
                ddA[2 * q2]      = ffma2(xda, l.x, ddA[2 * q2]);
                ddA[2 * q2 + 1]  = ffma2(xda, l.y, ddA[2 * q2 + 1]);
                ddB[2 * q2]      = ffma2(xdb, l.x, ddB[2 * q2]);
                ddB[2 * q2 + 1]  = ffma2(xdb, l.y, ddB[2 * q2 + 1]);
            }
        }
    }
    __syncthreads();

    // ---- stage Z slab (reuse buffer) ----
    {
        const float4* src = (const float4*)(Z + base * NIND);
#pragma unroll
        for (int i = 0; i < 16; ++i) {
            int idx = tid + 64 * i;
            float4 v = src[idx];
            int row = idx >> 3, c0 = (idx & 7) << 2;
            float* dst = &sStage[row * ROWSTRIDE + c0];
            dst[0] = v.x; dst[1] = v.y; dst[2] = v.z; dst[3] = v.w;
        }
    }
    __syncthreads();

    // ---- Phase 1b: Z-loop  (rhs += Theta*z)
#pragma unroll 1
    for (int c = 0; c < NIND / 4; ++c) {
#pragma unroll
        for (int kk = 0; kk < 4; ++kk) {
            int kz = 4 * c + kk;
            int k  = NIND + kz;
            u64 xda = dup2(rowA[kz]);
            u64 xdb = dup2(rowB[kz]);
#pragma unroll
            for (int q2 = 0; q2 < 4; ++q2) {
                ulonglong2 w = sW2[k][q2];
                rhsA[2 * q2]     = ffma2(xda, w.x, rhsA[2 * q2]);
                rhsA[2 * q2 + 1] = ffma2(xda, w.y, rhsA[2 * q2 + 1]);
                rhsB[2 * q2]     = ffma2(xdb, w.x, rhsB[2 * q2]);
                rhsB[2 * q2 + 1] = ffma2(xdb, w.y, rhsB[2 * q2 + 1]);
            }
        }
    }

    // ---- Phase 2: Dg_i = (1+eps - Gamma_ii) - d_i ; cc = rhs/Dg ; keep +invDg
    u64 ccA[8], ccB[8], invA[8], invB[8], yA[8], yB[8];
#pragma unroll
    for (int q = 0; q < 8; ++q) {
        float g0, g1; unpack2(sGd2[q], g0, g1);
        float da0, da1, ra0, ra1;
        unpack2(ddA[q], da0, da1); unpack2(rhsA[q], ra0, ra1);
        float ia0 = frcp(g0 - da0), ia1 = frcp(g1 - da1);
        ccA[q]  = pack2(ra0 * ia0, ra1 * ia1);
        invA[q] = pack2(ia0, ia1);
        yA[q]   = ccA[q];
        float db0, db1, rb0, rb1;
        unpack2(ddB[q], db0, db1); unpack2(rhsB[q], rb0, rb1);
        float ib0 = frcp(g0 - db0), ib1 = frcp(g1 - db1);
        ccB[q]  = pack2(rb0 * ib0, rb1 * ib1);
        invB[q] = pack2(ib0, ib1);
        yB[q]   = ccB[q];
    }

    // ---- Phase 3: Neumann iterations  y <- cc + invDg*(GammaOff*y)
#pragma unroll 1
    for (int it = 0; it < ITERS; ++it) {
        u64 accA[8], accB[8];
#pragma unroll
        for (int q = 0; q < 8; ++q) { accA[q] = 0ull; accB[q] = 0ull; }
#pragma unroll
        for (int j = 0; j < NDEP; ++j) {
            float a0, a1; unpack2(yA[j >> 1], a0, a1);
            u64 yda = dup2((j & 1) ? a1 : a0);
            float b0, b1; unpack2(yB[j >> 1], b0, b1);
            u64 ydb = dup2((j & 1) ? b1 : b0);
#pragma unroll
            for (int q2 = 0; q2 < 4; ++q2) {
                ulonglong2 o = sOff2[j][q2];
                accA[2 * q2]     = ffma2(yda, o.x, accA[2 * q2]);
                accA[2 * q2 + 1] = ffma2(yda, o.y, accA[2 * q2 + 1]);
                accB[2 * q2]     = ffma2(ydb, o.x, accB[2 * q2]);
                accB[2 * q2 + 1] = ffma2(ydb, o.y, accB[2 * q2 + 1]);
            }
        }
#pragma unroll
        for (int q = 0; q < 8; ++q) {
            yA[q] = ffma2(invA[q], accA[q], ccA[q]);
            yB[q] = ffma2(invB[q], accB[q], ccB[q]);
        }
    }

    // ---- Store: row-packed pairs are already in output order -> STG.128
    const size_t ea = base + tid;
    const size_t eb = base + 64 + tid;
    ulonglong2* ova = (ulonglong2*)(out + ea * NDEP);
    ulonglong2* ovb = (ulonglong2*)(out + eb * NDEP);
#pragma unroll
    for (int q = 0; q < 4; ++q) ova[q] = make_ulonglong2(yA[2 * q], yA[2 * q + 1]);
#pragma unroll
    for (int q = 0; q < 4; ++q) ovb[q] = make_ulonglong2(yB[2 * q], yB[2 * q + 1]);
}

extern "C" void kernel_launch(void* const* d_in, const int* in_sizes, int n_in,
                              void* d_out, int out_size)
{
    const float* X  = (const float*)d_in[0];
    const float* Z  = (const float*)d_in[1];
    const float* Up = (const float*)d_in[2];
    const float* Bm = (const float*)d_in[3];
    const float* Th = (const float*)d_in[4];
    const float* Ga = (const float*)d_in[5];
    const float* La = (const float*)d_in[6];
    float* out = (float*)d_out;

    const int threads = 64;
    const int blocks  = BATCH / 128;   // 2 elements per thread
    clefo_kernel<<<blocks, threads>>>(X, Z, Up, Bm, Th, Ga, La, out);
}

// round 7
// speedup vs baseline: 4.2032x; 1.4146x over previous
#include <cuda_runtime.h>

#define BATCH   262144
#define NIND    32
#define NDEP    16
#define EPSV    1e-7f
#define ITERS   2

typedef unsigned long long u64;

// ---- packed f32x2 helpers (Blackwell sm_103a) ----
__device__ __forceinline__ u64 pack2(float a, float b) {
    u64 r; asm("mov.b64 %0, {%1, %2};" : "=l"(r) : "f"(a), "f"(b)); return r;
}
__device__ __forceinline__ u64 dup2(float a) {
    u64 r; asm("mov.b64 %0, {%1, %1};" : "=l"(r) : "f"(a)); return r;
}
__device__ __forceinline__ void unpack2(u64 v, float &a, float &b) {
    asm("mov.b64 {%0, %1}, %2;" : "=f"(a), "=f"(b) : "l"(v));
}
__device__ __forceinline__ u64 ffma2(u64 a, u64 b, u64 c) {
    u64 d; asm("fma.rn.f32x2 %0, %1, %2, %3;" : "=l"(d) : "l"(a), "l"(b), "l"(c));
    return d;
}
__device__ __forceinline__ u64 mul2(u64 a, u64 b) {
    u64 d; asm("mul.rn.f32x2 %0, %1, %2;" : "=l"(d) : "l"(a), "l"(b));
    return d;
}
__device__ __forceinline__ float frcp(float x) {
    float r; asm("rcp.approx.f32 %0, %1;" : "=f"(r) : "f"(x)); return r;
}

// Pre-transformed weights: row-paired u64 for direct f32x2 operands.
struct CWeights {
    ulonglong2 W2[2 * NIND][4];   // [k][q2]: rows (4q2..4q2+3) paired; k<32->Bmat, else Theta
    ulonglong2 L2[NIND][4];       // Lam
    ulonglong2 Off2[NDEP][4];     // column j, rows paired; +Gamma off-diag, 0 diag
    u64 Gd2[8];                   // (1+eps - Gamma_ii) pairs
    u64 Ups2[8];
};

__device__ CWeights g_scratch;    // written by prep kernel
__constant__ CWeights cw;         // copied from g_scratch before main kernel

// ---- prep kernel: transform raw weights into g_scratch layout ----
__global__ void prep_kernel(const float* __restrict__ Ups, const float* __restrict__ Bm,
                            const float* __restrict__ Th,  const float* __restrict__ Ga,
                            const float* __restrict__ La)
{
    const int tid = threadIdx.x;
    for (int idx = tid; idx < 2 * NIND * 8; idx += 64) {
        int k = idx >> 3, j2 = idx & 7;
        int r0 = 2 * j2, r1 = r0 + 1;
        float w0, w1;
        if (k < NIND) { w0 = Bm[r0 * NIND + k];          w1 = Bm[r1 * NIND + k]; }
        else          { w0 = Th[r0 * NIND + (k - NIND)]; w1 = Th[r1 * NIND + (k - NIND)]; }
        ((u64*)&g_scratch.W2[k][0])[j2] = pack2(w0, w1);
    }
    for (int idx = tid; idx < NIND * 8; idx += 64) {
        int k = idx >> 3, j2 = idx & 7;
        ((u64*)&g_scratch.L2[k][0])[j2] =
            pack2(La[(2 * j2) * NIND + k], La[(2 * j2 + 1) * NIND + k]);
    }
    for (int idx = tid; idx < NDEP * 8; idx += 64) {
        int j = idx >> 3, i2 = idx & 7;
        int i0 = 2 * i2, i1 = i0 + 1;
        float v0 = (i0 == j) ? 0.0f : Ga[i0 * NDEP + j];
        float v1 = (i1 == j) ? 0.0f : Ga[i1 * NDEP + j];
        ((u64*)&g_scratch.Off2[j][0])[i2] = pack2(v0, v1);
    }
    if (tid < 8) {
        g_scratch.Ups2[tid] = pack2(Ups[2 * tid], Ups[2 * tid + 1]);
        g_scratch.Gd2[tid]  = pack2(1.0f + EPSV - Ga[(2 * tid) * NDEP + 2 * tid],
                                    1.0f + EPSV - Ga[(2 * tid + 1) * NDEP + 2 * tid + 1]);
    }
}

#define ROWSTRIDE 33   // floats per staged row (conflict-free scalar access)

// TWO batch elements per thread; f32x2 packs OUTPUT ROWS (2i, 2i+1).
// Weights come from __constant__ (uniform-const port) — zero crossbar traffic.
// Neumann (rhs-form): acc = rhs + GammaOff*y ; y = invDg (*) acc
__global__ __launch_bounds__(64, 6)
void clefo_kernel(const float* __restrict__ X, const float* __restrict__ Z,
                  float* __restrict__ out)
{
    __shared__ float sStage[128 * ROWSTRIDE]; // one block-slab of X or Z (reused)

    const int tid = threadIdx.x;
    const size_t base = (size_t)blockIdx.x * 128;

    // ---- stage X slab (coalesced global -> padded smem) ----
    {
        const float4* src = (const float4*)(X + base * NIND);
#pragma unroll
        for (int i = 0; i < 16; ++i) {
            int idx = tid + 64 * i;                  // float4 index in slab
            float4 v = src[idx];
            int row = idx >> 3, c0 = (idx & 7) << 2;
            float* dst = &sStage[row * ROWSTRIDE + c0];
            dst[0] = v.x; dst[1] = v.y; dst[2] = v.z; dst[3] = v.w;
        }
    }
    __syncthreads();

    // ---- Phase 1a: X-loop  (rhs += Bm*x ; d = La*x), rows packed in pairs
    u64 rhsA[8], rhsB[8], ddA[8], ddB[8];
#pragma unroll
    for (int q = 0; q < 8; ++q) {
        rhsA[q] = cw.Ups2[q]; rhsB[q] = cw.Ups2[q];
        ddA[q] = 0ull;        ddB[q] = 0ull;
    }
    const float* rowA = &sStage[tid * ROWSTRIDE];
    const float* rowB = &sStage[(tid + 64) * ROWSTRIDE];

#pragma unroll 1
    for (int c = 0; c < NIND / 4; ++c) {
#pragma unroll
        for (int kk = 0; kk < 4; ++kk) {
            int k = 4 * c + kk;
            u64 xda = dup2(rowA[k]);
            u64 xdb = dup2(rowB[k]);
#pragma unroll
            for (int q2 = 0; q2 < 4; ++q2) {
                ulonglong2 w = cw.W2[k][q2];
                rhsA[2 * q2]     = ffma2(xda, w.x, rhsA[2 * q2]);
                rhsA[2 * q2 + 1] = ffma2(xda, w.y, rhsA[2 * q2 + 1]);
                rhsB[2 * q2]     = ffma2(xdb, w.x, rhsB[2 * q2]);
                rhsB[2 * q2 + 1] = ffma2(xdb, w.y, rhsB[2 * q2 + 1]);
                ulonglong2 l = cw.L2[k][q2];
                ddA[2 * q2]      = ffma2(xda, l.x, ddA[2 * q2]);
                ddA[2 * q2 + 1]  = ffma2(xda, l.y, ddA[2 * q2 + 1]);
                ddB[2 * q2]      = ffma2(xdb, l.x, ddB[2 * q2]);
                ddB[2 * q2 + 1]  = ffma2(xdb, l.y, ddB[2 * q2 + 1]);
            }
        }
    }
    __syncthreads();

    // ---- stage Z slab (reuse buffer) ----
    {
        const float4* src = (const float4*)(Z + base * NIND);
#pragma unroll
        for (int i = 0; i < 16; ++i) {
            int idx = tid + 64 * i;
            float4 v = src[idx];
            int row = idx >> 3, c0 = (idx & 7) << 2;
            float* dst = &sStage[row * ROWSTRIDE + c0];
            dst[0] = v.x; dst[1] = v.y; dst[2] = v.z; dst[3] = v.w;
        }
    }
    __syncthreads();

    // ---- Phase 1b: Z-loop  (rhs += Theta*z)
#pragma unroll 1
    for (int c = 0; c < NIND / 4; ++c) {
#pragma unroll
        for (int kk = 0; kk < 4; ++kk) {
            int kz = 4 * c + kk;
            int k  = NIND + kz;
            u64 xda = dup2(rowA[kz]);
            u64 xdb = dup2(rowB[kz]);
#pragma unroll
            for (int q2 = 0; q2 < 4; ++q2) {
                ulonglong2 w = cw.W2[k][q2];
                rhsA[2 * q2]     = ffma2(xda, w.x, rhsA[2 * q2]);
                rhsA[2 * q2 + 1] = ffma2(xda, w.y, rhsA[2 * q2 + 1]);
                rhsB[2 * q2]     = ffma2(xdb, w.x, rhsB[2 * q2]);
                rhsB[2 * q2 + 1] = ffma2(xdb, w.y, rhsB[2 * q2 + 1]);
            }
        }
    }

    // ---- Phase 2: Dg_i = (1+eps - Gamma_ii) - d_i ; inv = 1/Dg ; y0 = inv*rhs
    u64 invA[8], invB[8], yA[8], yB[8];
#pragma unroll
    for (int q = 0; q < 8; ++q) {
        float g0, g1; unpack2(cw.Gd2[q], g0, g1);
        float da0, da1, db0, db1;
        unpack2(ddA[q], da0, da1);
        unpack2(ddB[q], db0, db1);
        invA[q] = pack2(frcp(g0 - da0), frcp(g1 - da1));
        invB[q] = pack2(frcp(g0 - db0), frcp(g1 - db1));
        yA[q]   = mul2(invA[q], rhsA[q]);
        yB[q]   = mul2(invB[q], rhsB[q]);
    }

    // ---- Phase 3: Neumann iterations  acc = rhs + GammaOff*y ; y = inv (*) acc
#pragma unroll 1
    for (int it = 0; it < ITERS; ++it) {
        u64 accA[8], accB[8];
#pragma unroll
        for (int q = 0; q < 8; ++q) { accA[q] = rhsA[q]; accB[q] = rhsB[q]; }
#pragma unroll
        for (int j = 0; j < NDEP; ++j) {
            float a0, a1; unpack2(yA[j >> 1], a0, a1);
            u64 yda = dup2((j & 1) ? a1 : a0);
            float b0, b1; unpack2(yB[j >> 1], b0, b1);
            u64 ydb = dup2((j & 1) ? b1 : b0);
#pragma unroll
            for (int q2 = 0; q2 < 4; ++q2) {
                ulonglong2 o = cw.Off2[j][q2];
                accA[2 * q2]     = ffma2(yda, o.x, accA[2 * q2]);
                accA[2 * q2 + 1] = ffma2(yda, o.y, accA[2 * q2 + 1]);
                accB[2 * q2]     = ffma2(ydb, o.x, accB[2 * q2]);
                accB[2 * q2 + 1] = ffma2(ydb, o.y, accB[2 * q2 + 1]);
            }
        }
#pragma unroll
        for (int q = 0; q < 8; ++q) {
            yA[q] = mul2(invA[q], accA[q]);
            yB[q] = mul2(invB[q], accB[q]);
        }
    }

    // ---- Store: row-packed pairs are already in output order -> STG.128
    const size_t ea = base + tid;
    const size_t eb = base + 64 + tid;
    ulonglong2* ova = (ulonglong2*)(out + ea * NDEP);
    ulonglong2* ovb = (ulonglong2*)(out + eb * NDEP);
#pragma unroll
    for (int q = 0; q < 4; ++q) ova[q] = make_ulonglong2(yA[2 * q], yA[2 * q + 1]);
#pragma unroll
    for (int q = 0; q < 4; ++q) ovb[q] = make_ulonglong2(yB[2 * q], yB[2 * q + 1]);
}

extern "C" void kernel_launch(void* const* d_in, const int* in_sizes, int n_in,
                              void* d_out, int out_size)
{
    const float* X  = (const float*)d_in[0];
    const float* Z  = (const float*)d_in[1];
    const float* Up = (const float*)d_in[2];
    const float* Bm = (const float*)d_in[3];
    const float* Th = (const float*)d_in[4];
    const float* Ga = (const float*)d_in[5];
    const float* La = (const float*)d_in[6];
    float* out = (float*)d_out;

    // 1) transform weights into device scratch
    prep_kernel<<<1, 64>>>(Up, Bm, Th, Ga, La);

    // 2) copy transformed weights into the constant bank (D2D, capturable)
    void* sp = nullptr;
    cudaGetSymbolAddress(&sp, g_scratch);
    cudaMemcpyToSymbolAsync(cw, sp, sizeof(CWeights), 0,
                            cudaMemcpyDeviceToDevice, 0);

    // 3) main kernel
    const int threads = 64;
    const int blocks  = BATCH / 128;   // 2 elements per thread
    clefo_kernel<<<blocks, threads>>>(X, Z, out);
}

// round 8
// speedup vs baseline: 4.5378x; 1.0796x over previous
#include <cuda_runtime.h>

#define BATCH   262144
#define NIND    32
#define NDEP    16
#define EPSV    1e-7f
#define ITERS   2

typedef unsigned long long u64;

// ---- packed f32x2 helpers (Blackwell sm_103a) ----
__device__ __forceinline__ u64 pack2(float a, float b) {
    u64 r; asm("mov.b64 %0, {%1, %2};" : "=l"(r) : "f"(a), "f"(b)); return r;
}
__device__ __forceinline__ u64 dup2(float a) {
    u64 r; asm("mov.b64 %0, {%1, %1};" : "=l"(r) : "f"(a)); return r;
}
__device__ __forceinline__ void unpack2(u64 v, float &a, float &b) {
    asm("mov.b64 {%0, %1}, %2;" : "=f"(a), "=f"(b) : "l"(v));
}
__device__ __forceinline__ u64 ffma2(u64 a, u64 b, u64 c) {
    u64 d; asm("fma.rn.f32x2 %0, %1, %2, %3;" : "=l"(d) : "l"(a), "l"(b), "l"(c));
    return d;
}
__device__ __forceinline__ u64 mul2(u64 a, u64 b) {
    u64 d; asm("mul.rn.f32x2 %0, %1, %2;" : "=l"(d) : "l"(a), "l"(b));
    return d;
}
__device__ __forceinline__ float frcp(float x) {
    float r; asm("rcp.approx.f32 %0, %1;" : "=f"(r) : "f"(x)); return r;
}

// Pre-transformed weights: row-paired u64 for direct f32x2 operands.
struct CWeights {
    ulonglong2 W2[2 * NIND][4];   // [k][q2]: rows (4q2..4q2+3) paired; k<32->Bmat, else Theta
    ulonglong2 L2[NIND][4];       // Lam
    ulonglong2 Off2[NDEP][4];     // column j, rows paired; +Gamma off-diag, 0 diag
    u64 Gd2[8];                   // (1+eps - Gamma_ii) pairs
    u64 Ups2[8];
};

__device__ CWeights g_scratch;    // written by prep kernel
__constant__ CWeights cw;         // copied from g_scratch before main kernel

// ---- prep kernel: transform raw weights into g_scratch layout ----
__global__ void prep_kernel(const float* __restrict__ Ups, const float* __restrict__ Bm,
                            const float* __restrict__ Th,  const float* __restrict__ Ga,
                            const float* __restrict__ La)
{
    const int tid = threadIdx.x;
    for (int idx = tid; idx < 2 * NIND * 8; idx += 64) {
        int k = idx >> 3, j2 = idx & 7;
        int r0 = 2 * j2, r1 = r0 + 1;
        float w0, w1;
        if (k < NIND) { w0 = Bm[r0 * NIND + k];          w1 = Bm[r1 * NIND + k]; }
        else          { w0 = Th[r0 * NIND + (k - NIND)]; w1 = Th[r1 * NIND + (k - NIND)]; }
        ((u64*)&g_scratch.W2[k][0])[j2] = pack2(w0, w1);
    }
    for (int idx = tid; idx < NIND * 8; idx += 64) {
        int k = idx >> 3, j2 = idx & 7;
        ((u64*)&g_scratch.L2[k][0])[j2] =
            pack2(La[(2 * j2) * NIND + k], La[(2 * j2 + 1) * NIND + k]);
    }
    for (int idx = tid; idx < NDEP * 8; idx += 64) {
        int j = idx >> 3, i2 = idx & 7;
        int i0 = 2 * i2, i1 = i0 + 1;
        float v0 = (i0 == j) ? 0.0f : Ga[i0 * NDEP + j];
        float v1 = (i1 == j) ? 0.0f : Ga[i1 * NDEP + j];
        ((u64*)&g_scratch.Off2[j][0])[i2] = pack2(v0, v1);
    }
    if (tid < 8) {
        g_scratch.Ups2[tid] = pack2(Ups[2 * tid], Ups[2 * tid + 1]);
        g_scratch.Gd2[tid]  = pack2(1.0f + EPSV - Ga[(2 * tid) * NDEP + 2 * tid],
                                    1.0f + EPSV - Ga[(2 * tid + 1) * NDEP + 2 * tid + 1]);
    }
}

#define ROWSTRIDE 33   // floats per staged row (conflict-free scalar access)
#define TPB       128  // threads per block, one element each

// ONE batch element per thread; f32x2 packs OUTPUT ROWS (2i, 2i+1).
// Weights come from __constant__ (uniform-const port) — zero crossbar traffic.
// Neumann (rhs-form): acc = rhs + GammaOff*y ; y = invDg (*) acc
__global__ __launch_bounds__(TPB, 5)
void clefo_kernel(const float* __restrict__ X, const float* __restrict__ Z,
                  float* __restrict__ out)
{
    __shared__ float sStage[TPB * ROWSTRIDE]; // one block-slab of X or Z (reused)

    const int tid = threadIdx.x;
    const size_t base = (size_t)blockIdx.x * TPB;

    // ---- stage X slab (coalesced global -> padded smem) ----
    {
        const float4* src = (const float4*)(X + base * NIND);
#pragma unroll
        for (int i = 0; i < 8; ++i) {
            int idx = tid + TPB * i;                 // float4 index in slab
            float4 v = src[idx];
            int row = idx >> 3, c0 = (idx & 7) << 2;
            float* dst = &sStage[row * ROWSTRIDE + c0];
            dst[0] = v.x; dst[1] = v.y; dst[2] = v.z; dst[3] = v.w;
        }
    }
    __syncthreads();

    // ---- Phase 1a: X-loop  (rhs += Bm*x ; d = La*x), rows packed in pairs
    u64 rhs[8], dd[8];
#pragma unroll
    for (int q = 0; q < 8; ++q) { rhs[q] = cw.Ups2[q]; dd[q] = 0ull; }
    const float* row = &sStage[tid * ROWSTRIDE];

#pragma unroll 1
    for (int c = 0; c < NIND / 4; ++c) {
#pragma unroll
        for (int kk = 0; kk < 4; ++kk) {
            int k = 4 * c + kk;
            u64 xd = dup2(row[k]);
#pragma unroll
            for (int q2 = 0; q2 < 4; ++q2) {
                ulonglong2 w = cw.W2[k][q2];
                rhs[2 * q2]     = ffma2(xd, w.x, rhs[2 * q2]);
                rhs[2 * q2 + 1] = ffma2(xd, w.y, rhs[2 * q2 + 1]);
                ulonglong2 l = cw.L2[k][q2];
                dd[2 * q2]      = ffma2(xd, l.x, dd[2 * q2]);
                dd[2 * q2 + 1]  = ffma2(xd, l.y, dd[2 * q2 + 1]);
            }
        }
    }
    __syncthreads();

    // ---- stage Z slab (reuse buffer) ----
    {
        const float4* src = (const float4*)(Z + base * NIND);
#pragma unroll
        for (int i = 0; i < 8; ++i) {
            int idx = tid + TPB * i;
            float4 v = src[idx];
            int r = idx >> 3, c0 = (idx & 7) << 2;
            float* dst = &sStage[r * ROWSTRIDE + c0];
            dst[0] = v.x; dst[1] = v.y; dst[2] = v.z; dst[3] = v.w;
        }
    }
    __syncthreads();

    // ---- Phase 1b: Z-loop  (rhs += Theta*z)
#pragma unroll 1
    for (int c = 0; c < NIND / 4; ++c) {
#pragma unroll
        for (int kk = 0; kk < 4; ++kk) {
            int kz = 4 * c + kk;
            int k  = NIND + kz;
            u64 xd = dup2(row[kz]);
#pragma unroll
            for (int q2 = 0; q2 < 4; ++q2) {
                ulonglong2 w = cw.W2[k][q2];
                rhs[2 * q2]     = ffma2(xd, w.x, rhs[2 * q2]);
                rhs[2 * q2 + 1] = ffma2(xd, w.y, rhs[2 * q2 + 1]);
            }
        }
    }

    // ---- Phase 2: Dg_i = (1+eps - Gamma_ii) - d_i ; inv = 1/Dg ; y0 = inv*rhs
    u64 inv[8], y[8];
#pragma unroll
    for (int q = 0; q < 8; ++q) {
        float g0, g1; unpack2(cw.Gd2[q], g0, g1);
        float d0, d1; unpack2(dd[q], d0, d1);
        inv[q] = pack2(frcp(g0 - d0), frcp(g1 - d1));
        y[q]   = mul2(inv[q], rhs[q]);
    }

    // ---- Phase 3: Neumann iterations  acc = rhs + GammaOff*y ; y = inv (*) acc
#pragma unroll 1
    for (int it = 0; it < ITERS; ++it) {
        u64 acc[8];
#pragma unroll
        for (int q = 0; q < 8; ++q) acc[q] = rhs[q];
#pragma unroll
        for (int j = 0; j < NDEP; ++j) {
            float a0, a1; unpack2(y[j >> 1], a0, a1);
            u64 yd = dup2((j & 1) ? a1 : a0);
#pragma unroll
            for (int q2 = 0; q2 < 4; ++q2) {
                ulonglong2 o = cw.Off2[j][q2];
                acc[2 * q2]     = ffma2(yd, o.x, acc[2 * q2]);
                acc[2 * q2 + 1] = ffma2(yd, o.y, acc[2 * q2 + 1]);
            }
        }
#pragma unroll
        for (int q = 0; q < 8; ++q) y[q] = mul2(inv[q], acc[q]);
    }

    // ---- Store: row-packed pairs are already in output order -> STG.128
    ulonglong2* ov = (ulonglong2*)(out + (base + tid) * NDEP);
#pragma unroll
    for (int q = 0; q < 4; ++q) ov[q] = make_ulonglong2(y[2 * q], y[2 * q + 1]);
}

extern "C" void kernel_launch(void* const* d_in, const int* in_sizes, int n_in,
                              void* d_out, int out_size)
{
    const float* X  = (const float*)d_in[0];
    const float* Z  = (const float*)d_in[1];
    const float* Up = (const float*)d_in[2];
    const float* Bm = (const float*)d_in[3];
    const float* Th = (const float*)d_in[4];
    const float* Ga = (const float*)d_in[5];
    const float* La = (const float*)d_in[6];
    float* out = (float*)d_out;

    // 1) transform weights into device scratch
    prep_kernel<<<1, 64>>>(Up, Bm, Th, Ga, La);

    // 2) copy transformed weights into the constant bank (D2D, capturable)
    void* sp = nullptr;
    cudaGetSymbolAddress(&sp, g_scratch);
    cudaMemcpyToSymbolAsync(cw, sp, sizeof(CWeights), 0,
                            cudaMemcpyDeviceToDevice, 0);

    // 3) main kernel: one element per thread
    const int blocks = BATCH / TPB;
    clefo_kernel<<<blocks, TPB>>>(X, Z, out);
}